// round 1
// baseline (speedup 1.0000x reference)
#include <cuda_runtime.h>

// Spline2D: out[b,i,j] = sum_{u,v} bx[u]*by[v]*coeffs[u+2+r, v+2+c],
//   r = i - px - 96, c = j - py - 96, valid for r,c in [0,64]; else 0.
// px = floor(x[b]), sx = x[b]-floor(x[b]) (ditto y). Cubic B-spline basis.
//
// One block per batch element:
//   stage 1: rowblend rb[r][cc] = sum_u bx[u]*coeffs[r+2+u][cc+2]   (65 x 68, smem)
//   stage 2: tpl[r][c]          = sum_v by[v]*rb[r][c+v]            (65 x 65, smem)
//   stage 3: stream 256x256 fp32 tile to gmem as float4 (zeros outside window)

#define OH 256
#define OW 256
#define CO 72      // coeffs leading dim (64 + 2*4 pad)

__global__ __launch_bounds__(512, 2) void spline2d_kernel(
    const float* __restrict__ coeffs,
    const float* __restrict__ xv,
    const float* __restrict__ yv,
    float* __restrict__ out)
{
    __shared__ float rb [65 * 68];   // rowblend, stride 68
    __shared__ float tpl[65 * 66];   // template, stride 66 (pad vs bank conflicts)

    const int b = blockIdx.x;
    const float x = xv[b], y = yv[b];
    const float fx = floorf(x), fy = floorf(y);
    const int   px = (int)fx,  py = (int)fy;
    const float sx = x - fx,   sy = y - fy;

    // cubic B-spline basis (matches reference bspline3 exactly in fp32)
    float bx0, bx1, bx2, bx3, by0, by1, by2, by3;
    {
        const float p = sx, p2 = p * p, p3 = p2 * p, q = 1.0f - p;
        bx0 = p3 * (1.0f / 6.0f);
        bx1 = -0.5f * p3 + 0.5f * p2 + 0.5f * p + (1.0f / 6.0f);
        bx2 =  0.5f * p3 - p2 + (2.0f / 3.0f);
        bx3 = q * q * q * (1.0f / 6.0f);
    }
    {
        const float p = sy, p2 = p * p, p3 = p2 * p, q = 1.0f - p;
        by0 = p3 * (1.0f / 6.0f);
        by1 = -0.5f * p3 + 0.5f * p2 + 0.5f * p + (1.0f / 6.0f);
        by2 =  0.5f * p3 - p2 + (2.0f / 3.0f);
        by3 = q * q * q * (1.0f / 6.0f);
    }

    const int t = threadIdx.x;

    // ---- stage 1: rowblend (65*68 = 4420 items) ----
    for (int idx = t; idx < 65 * 68; idx += 512) {
        const int r  = idx / 68;
        const int cc = idx - r * 68;
        const float* cp = coeffs + (r + 2) * CO + (cc + 2);
        rb[idx] = bx0 * cp[0] + bx1 * cp[CO] + bx2 * cp[2 * CO] + bx3 * cp[3 * CO];
    }
    __syncthreads();

    // ---- stage 2: column blend into template (65*65 = 4225 items) ----
    for (int idx = t; idx < 65 * 65; idx += 512) {
        const int r = idx / 65;
        const int c = idx - r * 65;
        const float* rp = rb + r * 68 + c;
        tpl[r * 66 + c] = by0 * rp[0] + by1 * rp[1] + by2 * rp[2] + by3 * rp[3];
    }
    __syncthreads();

    // ---- stage 3: stream 256x256 tile (16384 float4s) ----
    float4* outp = (float4*)(out + (size_t)b * (OH * OW));
    const int rbase = px + 96;   // out row i -> template row i - rbase
    const int cbase = py + 96;   // out col j -> template col j - cbase

    #pragma unroll 4
    for (int q = t; q < (OH * OW) / 4; q += 512) {
        const int i  = q >> 6;            // row (64 float4 per row)
        const int j0 = (q & 63) << 2;     // starting column of this float4
        float4 v = make_float4(0.f, 0.f, 0.f, 0.f);
        const int r = i - rbase;
        if ((unsigned)r <= 64u) {
            const int c = j0 - cbase;
            const float* tp = tpl + r * 66;
            if (c >= 0 && c + 3 <= 64) {          // fully inside window (common case)
                v.x = tp[c]; v.y = tp[c + 1]; v.z = tp[c + 2]; v.w = tp[c + 3];
            } else {                               // window edge straddles the float4
                if ((unsigned)(c    ) <= 64u) v.x = tp[c];
                if ((unsigned)(c + 1) <= 64u) v.y = tp[c + 1];
                if ((unsigned)(c + 2) <= 64u) v.z = tp[c + 2];
                if ((unsigned)(c + 3) <= 64u) v.w = tp[c + 3];
            }
        }
        outp[q] = v;
    }
}

extern "C" void kernel_launch(void* const* d_in, const int* in_sizes, int n_in,
                              void* d_out, int out_size) {
    const float* coeffs = (const float*)d_in[0];   // (72,72) f32
    const float* x      = (const float*)d_in[1];   // (1024,1,1,1) f32
    const float* y      = (const float*)d_in[2];   // (1024,1,1,1) f32
    float* out          = (float*)d_out;           // (1024,1,256,256) f32

    const int batch = in_sizes[1];                 // 1024
    spline2d_kernel<<<batch, 512>>>(coeffs, x, y, out);
}